// round 10
// baseline (speedup 1.0000x reference)
#include <cuda_runtime.h>
#include <cuda_fp16.h>
#include <cstdint>

// Problem shape
#define B_DIM 64
#define T_DIM 512
#define D_DIM 1024
#define U_DIM 128
#define M_TOTAL (B_DIM * T_DIM)        // 32768
#define M_TILE  128
#define K_CHUNK 32
#define NUM_CHUNKS (D_DIM / K_CHUNK)   // 32
#define NUM_CTAS (M_TOTAL / M_TILE)    // 256
#define THREADS 256
#define STAGES  4

// SMEM layout
#define OFF_BIAS  0
#define OFF_LB    512
#define OFF_RB    1024
#define OFF_TILES 1536
#define A_BYTES  16384                  // 128 rows x 128B (32 fp32)
#define B_BYTES  8192                   // 128 rows x 64B (32 fp16)
#define STAGE_BYTES (A_BYTES + B_BYTES) // 24576
#define T_A 0
#define T_B A_BYTES
#define SMEM_TOTAL (OFF_TILES + STAGES * STAGE_BYTES)   // 99840

// Pre-converted B operand (kernel^T), K-major [U][D], fp16
__device__ __align__(16) __half g_Bh[U_DIM * D_DIM];

// ---------------- helpers ----------------
static __device__ __forceinline__ uint32_t smem_u32(const void* p) {
    uint32_t a;
    asm("{ .reg .u64 t; cvta.to.shared.u64 t, %1; cvt.u32.u64 %0, t; }" : "=r"(a) : "l"(p));
    return a;
}
// swizzled byte offset of 16B chunk c in row r (64B-wide fp16 tile)
static __device__ __forceinline__ uint32_t swzB(uint32_t r, uint32_t c) {
    return r * 64u + ((c ^ ((r >> 1) & 3u)) << 4);
}
// swizzled byte address within 128B-wide fp32 tile: row r, byte-in-row b
static __device__ __forceinline__ uint32_t swzA(uint32_t r, uint32_t b) {
    return r * 128u + (((b >> 4) ^ (r & 7u)) << 4) + (b & 15u);
}

#define LDMX4(R, addr) \
    asm volatile("ldmatrix.sync.aligned.m8n8.x4.shared.b16 {%0,%1,%2,%3}, [%4];" \
        : "=r"((R)[0]), "=r"((R)[1]), "=r"((R)[2]), "=r"((R)[3]) : "r"(addr))

// ld.shared.v2.f32 + pack to half2 (one fragment b32)
#define LDSA_CVT(dst, addr) do { \
    float _x, _y; \
    asm volatile("ld.shared.v2.f32 {%0,%1}, [%2];" : "=f"(_x), "=f"(_y) : "r"(addr)); \
    __half2 _h = __float22half2_rn(make_float2(_x, _y)); \
    (dst) = *reinterpret_cast<uint32_t*>(&_h); \
} while (0)

#define MMA_F16(acc, A0, A1, A2, A3, B0, B1) \
    asm volatile("mma.sync.aligned.m16n8k16.row.col.f32.f16.f16.f32 " \
        "{%0,%1,%2,%3}, {%4,%5,%6,%7}, {%8,%9}, {%0,%1,%2,%3};" \
        : "+f"((acc)[0]), "+f"((acc)[1]), "+f"((acc)[2]), "+f"((acc)[3]) \
        : "r"(A0), "r"(A1), "r"(A2), "r"(A3), "r"(B0), "r"(B1))

#define CP_ASYNC16(dst, src) \
    asm volatile("cp.async.cg.shared.global [%0], [%1], 16;" \
                 :: "r"(dst), "l"(src) : "memory")
#define CP_COMMIT() asm volatile("cp.async.commit_group;" ::: "memory")
#define CP_WAIT2()  asm volatile("cp.async.wait_group 2;" ::: "memory")

// ---------------- Prologue: kernel[D,U] -> g_Bh [U,D] fp16 ----------------
__global__ void crf_bprep_kernel(const float* __restrict__ kern) {
    int e = blockIdx.x * blockDim.x + threadIdx.x;   // e = u*D + d
    int u = e >> 10;
    int d = e & (D_DIM - 1);
    g_Bh[e] = __float2half(kern[d * U_DIM + u]);
}

// ---------------- Main fused GEMM + boundary epilogue ----------------
__global__ __launch_bounds__(THREADS, 2) void crf_gemm_kernel(
    const float* __restrict__ x, const int* __restrict__ mask,
    const float* __restrict__ bias, const float* __restrict__ lb,
    const float* __restrict__ rb, float* __restrict__ out)
{
    extern __shared__ char smem[];
    const uint32_t smem_base = smem_u32(smem);
    const int tid = threadIdx.x;
    const int wid = tid >> 5;
    const int lid = tid & 31;
    const int warp_m = (wid & 3) * 32;   // 4 warps along M (m32 each)
    const int warp_n = (wid >> 2) * 64;  // 2 warps along N (n64 each)

    // stage bias / boundary vectors
    if (tid < U_DIM) {
        ((float*)(smem + OFF_BIAS))[tid] = bias[tid];
        ((float*)(smem + OFF_LB))[tid]   = lb[tid];
        ((float*)(smem + OFF_RB))[tid]   = rb[tid];
    }

    // per-lane A fragment LDS addresses (fp32 tile, constant across chunks)
    // fragment a0:(r0,c) a1:(r1,c) a2:(r0,c+8) a3:(r1,c+8); c = (lid&3)*2, k-halves via ks
    uint32_t a_ls[2][2][4];   // [mb][ks][reg]
    #pragma unroll
    for (int mb = 0; mb < 2; mb++)
        #pragma unroll
        for (int ks = 0; ks < 2; ks++) {
            uint32_t r0 = warp_m + mb * 16 + (lid >> 2);
            uint32_t r1 = r0 + 8;
            uint32_t b0 = ks * 64u + (lid & 3) * 8u;   // byte offset of col pair
            a_ls[mb][ks][0] = swzA(r0, b0);
            a_ls[mb][ks][1] = swzA(r1, b0);
            a_ls[mb][ks][2] = swzA(r0, b0 + 32u);
            a_ls[mb][ks][3] = swzA(r1, b0 + 32u);
        }
    // per-lane B ldmatrix offsets
    uint32_t b_off[4][2];   // [g][ks]
    #pragma unroll
    for (int g = 0; g < 4; g++)
        #pragma unroll
        for (int ks = 0; ks < 2; ks++) {
            uint32_t n = warp_n + g * 16 + (lid & 7) + ((lid >> 4) & 1) * 8;
            uint32_t c = ks * 2 + ((lid >> 3) & 1);
            b_off[g][ks] = swzB(n, c);
        }

    const float* xblk = x + (size_t)blockIdx.x * (M_TILE * D_DIM);
    const __half* gbh = g_Bh;

    float acc[2][8][4];
    #pragma unroll
    for (int mb = 0; mb < 2; mb++)
        #pragma unroll
        for (int nb = 0; nb < 8; nb++)
            #pragma unroll
            for (int i = 0; i < 4; i++) acc[mb][nb][i] = 0.0f;

    // issue one chunk's async copies (A fp32 + B fp16) into a stage
    auto ISSUE = [&](int kc) {
        const uint32_t sb = smem_base + OFF_TILES + (kc & (STAGES - 1)) * STAGE_BYTES;
        const int k0 = kc * K_CHUNK;
        #pragma unroll
        for (int j = 0; j < 4; j++) {       // A: 1024 16B chunks / 256 thr
            int f = tid + THREADS * j;
            int r = f >> 3, c = f & 7;      // 8 chunks per 128B row
            CP_ASYNC16(sb + T_A + swzA((uint32_t)r, (uint32_t)(c << 4)),
                       xblk + (size_t)r * D_DIM + k0 + c * 4);
        }
        #pragma unroll
        for (int j = 0; j < 2; j++) {       // B: 512 16B chunks / 256 thr
            int f = tid + THREADS * j;
            int n = f >> 2, s = f & 3;      // 4 chunks per 64B row
            CP_ASYNC16(sb + T_B + swzB((uint32_t)n, (uint32_t)s),
                       gbh + (size_t)n * D_DIM + k0 + s * 8);
        }
    };

    // pipeline prologue: chunks 0,1,2 in flight
    ISSUE(0); CP_COMMIT();
    ISSUE(1); CP_COMMIT();
    ISSUE(2); CP_COMMIT();

    for (int kc = 0; kc < NUM_CHUNKS; kc++) {
        CP_WAIT2();             // chunk kc landed (2 newer groups may be pending)
        __syncthreads();        // all warps see it; all done reading stage being reused

        if (kc + 3 < NUM_CHUNKS) ISSUE(kc + 3);
        CP_COMMIT();            // dummy group at tail keeps wait count uniform

        const uint32_t sb = smem_base + OFF_TILES + (kc & (STAGES - 1)) * STAGE_BYTES;
        const uint32_t sa = sb + T_A, sbh = sb + T_B;

        #pragma unroll
        for (int ks = 0; ks < 2; ks++) {
            uint32_t a0[4], a1[4];
            #pragma unroll
            for (int i = 0; i < 4; i++) LDSA_CVT(a0[i], sa + a_ls[0][ks][i]);
            #pragma unroll
            for (int i = 0; i < 4; i++) LDSA_CVT(a1[i], sa + a_ls[1][ks][i]);
            #pragma unroll
            for (int g = 0; g < 4; g++) {
                uint32_t bh[4];
                LDMX4(bh, sbh + b_off[g][ks]);
                #pragma unroll
                for (int h = 0; h < 2; h++) {
                    const int nb = g * 2 + h;
                    const uint32_t b0 = bh[2 * h], b1 = bh[2 * h + 1];
                    MMA_F16(acc[0][nb], a0[0], a0[1], a0[2], a0[3], b0, b1);
                    MMA_F16(acc[1][nb], a1[0], a1[1], a1[2], a1[3], b0, b1);
                }
            }
        }
    }

    // ---- epilogue: bias + mask-gated boundaries ----
    const float* sbias = (const float*)(smem + OFF_BIAS);
    const float* slb   = (const float*)(smem + OFF_LB);
    const float* srb   = (const float*)(smem + OFF_RB);
    const int gid = lid >> 2, tig = lid & 3;

    #pragma unroll
    for (int mb = 0; mb < 2; mb++) {
        #pragma unroll
        for (int p = 0; p < 2; p++) {
            int row = warp_m + mb * 16 + p * 8 + gid;
            int gm = blockIdx.x * M_TILE + row;
            int t = gm & (T_DIM - 1);
            int mc = mask[gm];
            int mp = (t > 0) ? mask[gm - 1] : 0;
            int mn = (t < T_DIM - 1) ? mask[gm + 1] : 0;
            float s = (mc > mp) ? 1.0f : 0.0f;
            float e = (mn > mc) ? 1.0f : 0.0f;
            float* orow = out + (size_t)gm * U_DIM;
            #pragma unroll
            for (int nb = 0; nb < 8; nb++) {
                int c = warp_n + nb * 8 + 2 * tig;
                float2 o;
                o.x = acc[mb][nb][2 * p + 0] + sbias[c + 0] + s * slb[c + 0] + e * srb[c + 0];
                o.y = acc[mb][nb][2 * p + 1] + sbias[c + 1] + s * slb[c + 1] + e * srb[c + 1];
                *reinterpret_cast<float2*>(orow + c) = o;
            }
        }
    }
}

extern "C" void kernel_launch(void* const* d_in, const int* in_sizes, int n_in,
                              void* d_out, int out_size) {
    const float* x    = (const float*)d_in[0];
    const int*   mask = (const int*)d_in[1];
    const float* kern = (const float*)d_in[2];
    const float* bias = (const float*)d_in[3];
    const float* lb   = (const float*)d_in[4];
    const float* rb   = (const float*)d_in[5];
    float* out = (float*)d_out;

    cudaFuncSetAttribute(crf_gemm_kernel,
                         cudaFuncAttributeMaxDynamicSharedMemorySize, SMEM_TOTAL);

    crf_bprep_kernel<<<(U_DIM * D_DIM) / 256, 256>>>(kern);
    crf_gemm_kernel<<<NUM_CTAS, THREADS, SMEM_TOTAL>>>(x, mask, bias, lb, rb, out);
}

// round 11
// speedup vs baseline: 1.6433x; 1.6433x over previous
#include <cuda_runtime.h>
#include <cuda_fp16.h>
#include <cstdint>

// Problem shape
#define B_DIM 64
#define T_DIM 512
#define D_DIM 1024
#define U_DIM 128
#define M_TOTAL (B_DIM * T_DIM)        // 32768
#define M_TILE  128
#define K_CHUNK 32
#define NUM_CHUNKS (D_DIM / K_CHUNK)   // 32
#define NUM_CTAS (M_TOTAL / M_TILE)    // 256
#define THREADS 256

// SMEM layout
#define OFF_BIAS  0
#define OFF_LB    512
#define OFF_RB    1024
#define OFF_TILES 1536
#define TILE_BYTES 8192                 // 128 rows x 64B (32 fp16)
#define A_STAGES 2
#define B_STAGES 3
#define OFF_A OFF_TILES
#define OFF_B (OFF_TILES + A_STAGES * TILE_BYTES)
#define SMEM_TOTAL (OFF_B + B_STAGES * TILE_BYTES)   // 42496

// Pre-converted B operand (kernel^T), K-major [U][D], fp16
__device__ __align__(16) __half g_Bh[U_DIM * D_DIM];

// ---------------- helpers ----------------
static __device__ __forceinline__ uint32_t smem_u32(const void* p) {
    uint32_t a;
    asm("{ .reg .u64 t; cvta.to.shared.u64 t, %1; cvt.u32.u64 %0, t; }" : "=r"(a) : "l"(p));
    return a;
}
static __device__ __forceinline__ uint32_t h2u(__half2 h) {
    return *reinterpret_cast<uint32_t*>(&h);
}
// swizzled byte offset of 16B chunk c (0..3) in row r of a 64B-wide tile
static __device__ __forceinline__ uint32_t swz(uint32_t r, uint32_t c) {
    return r * 64u + ((c ^ ((r >> 1) & 3u)) << 4);
}

#define LDMX4(R, addr) \
    asm volatile("ldmatrix.sync.aligned.m8n8.x4.shared.b16 {%0,%1,%2,%3}, [%4];" \
        : "=r"((R)[0]), "=r"((R)[1]), "=r"((R)[2]), "=r"((R)[3]) : "r"(addr))

#define MMA_F16(acc, A0, A1, A2, A3, B0, B1) \
    asm volatile("mma.sync.aligned.m16n8k16.row.col.f32.f16.f16.f32 " \
        "{%0,%1,%2,%3}, {%4,%5,%6,%7}, {%8,%9}, {%0,%1,%2,%3};" \
        : "+f"((acc)[0]), "+f"((acc)[1]), "+f"((acc)[2]), "+f"((acc)[3]) \
        : "r"(A0), "r"(A1), "r"(A2), "r"(A3), "r"(B0), "r"(B1))

#define CP_ASYNC16(dst, src) \
    asm volatile("cp.async.cg.shared.global [%0], [%1], 16;" \
                 :: "r"(dst), "l"(src) : "memory")
#define CP_COMMIT() asm volatile("cp.async.commit_group;" ::: "memory")
#define CP_WAIT1()  asm volatile("cp.async.wait_group 1;" ::: "memory")

// ---------------- Prologue: kernel[D,U] -> g_Bh [U,D] fp16 ----------------
__global__ void crf_bprep_kernel(const float* __restrict__ kern) {
    int e = blockIdx.x * blockDim.x + threadIdx.x;   // e = u*D + d
    int u = e >> 10;
    int d = e & (D_DIM - 1);
    g_Bh[e] = __float2half(kern[d * U_DIM + u]);
}

// ---------------- Main fused GEMM + boundary epilogue ----------------
__global__ __launch_bounds__(THREADS, 2) void crf_gemm_kernel(
    const float* __restrict__ x, const int* __restrict__ mask,
    const float* __restrict__ bias, const float* __restrict__ lb,
    const float* __restrict__ rb, float* __restrict__ out)
{
    extern __shared__ char smem[];
    const uint32_t smem_base = smem_u32(smem);
    const int tid = threadIdx.x;
    const int wid = tid >> 5;
    const int lid = tid & 31;
    const int warp_m = (wid & 3) * 32;   // 4 warps along M (m32 each)
    const int warp_n = (wid >> 2) * 64;  // 2 warps along N (n64 each)

    // stage bias / boundary vectors
    if (tid < U_DIM) {
        ((float*)(smem + OFF_BIAS))[tid] = bias[tid];
        ((float*)(smem + OFF_LB))[tid]   = lb[tid];
        ((float*)(smem + OFF_RB))[tid]   = rb[tid];
    }

    // per-lane ldmatrix offsets
    uint32_t a_off[2][2];   // [mb][ks]
    #pragma unroll
    for (int mb = 0; mb < 2; mb++)
        #pragma unroll
        for (int ks = 0; ks < 2; ks++) {
            uint32_t r = warp_m + mb * 16 + (lid & 15);
            uint32_t c = ks * 2 + (lid >> 4);
            a_off[mb][ks] = swz(r, c);
        }
    uint32_t b_off[4][2];   // [g][ks]
    #pragma unroll
    for (int g = 0; g < 4; g++)
        #pragma unroll
        for (int ks = 0; ks < 2; ks++) {
            uint32_t n = warp_n + g * 16 + (lid & 7) + ((lid >> 4) & 1) * 8;
            uint32_t c = ks * 2 + ((lid >> 3) & 1);
            b_off[g][ks] = swz(n, c);
        }

    const float* xblk = x + (size_t)blockIdx.x * (M_TILE * D_DIM);
    const __half* gbh = g_Bh;

    float acc[2][8][4];
    #pragma unroll
    for (int mb = 0; mb < 2; mb++)
        #pragma unroll
        for (int nb = 0; nb < 8; nb++)
            #pragma unroll
            for (int i = 0; i < 4; i++) acc[mb][nb][i] = 0.0f;

    float4 ax[4];

    auto LOADX = [&](int kc) {
        const int k0 = kc * K_CHUNK;
        #pragma unroll
        for (int j = 0; j < 4; j++) {
            int f = tid + THREADS * j;      // float4 index in 128x32 fp32 tile
            int r = f >> 3, c4 = f & 7;     // 8 float4 per row
            ax[j] = *reinterpret_cast<const float4*>(xblk + (size_t)r * D_DIM + k0 + c4 * 4);
        }
    };
    auto CPB = [&](int kc) {
        const uint32_t sb = smem_base + OFF_B + (kc % B_STAGES) * TILE_BYTES;
        const int k0 = kc * K_CHUNK;
        #pragma unroll
        for (int j = 0; j < 2; j++) {
            int f = tid + THREADS * j;      // 16B chunk index in 128x64B tile
            int n = f >> 2, s = f & 3;      // 4 chunks per row
            CP_ASYNC16(sb + swz((uint32_t)n, (uint32_t)s),
                       gbh + (size_t)n * D_DIM + k0 + s * 8);
        }
    };
    auto STSA = [&](int kc) {
        const uint32_t sb = smem_base + OFF_A + (kc & (A_STAGES - 1)) * TILE_BYTES;
        #pragma unroll
        for (int j = 0; j < 4; j++) {
            int f = tid + THREADS * j;
            int r = f >> 3, c4 = f & 7;
            float4 v = ax[j];
            __half2 h01 = __float22half2_rn(make_float2(v.x, v.y));
            __half2 h23 = __float22half2_rn(make_float2(v.z, v.w));
            uint32_t addr = swz((uint32_t)r, (uint32_t)(c4 >> 1)) + (c4 & 1) * 8;
            uint64_t hv = ((uint64_t)h2u(h23) << 32) | h2u(h01);
            asm volatile("st.shared.b64 [%0], %1;" :: "r"(sb + addr), "l"(hv) : "memory");
        }
    };

    // pipeline prologue: A(0) in smem, A(1) in regs, B(0),B(1) in flight
    LOADX(0);
    CPB(0); CP_COMMIT();
    CPB(1); CP_COMMIT();
    STSA(0);
    LOADX(1);
    CP_WAIT1();          // B(0) landed; B(1) may still be in flight
    __syncthreads();

    for (int kc = 0; kc < NUM_CHUNKS; kc++) {
        const uint32_t sa = smem_base + OFF_A + (kc & (A_STAGES - 1)) * TILE_BYTES;
        const uint32_t sbh = smem_base + OFF_B + (kc % B_STAGES) * TILE_BYTES;

        // ---- ks = 0 half: hides the in-flight LDGs of chunk kc+1 ----
        {
            uint32_t a0[4], a1[4];
            LDMX4(a0, sa + a_off[0][0]);
            LDMX4(a1, sa + a_off[1][0]);
            #pragma unroll
            for (int g = 0; g < 4; g++) {
                uint32_t bh[4];
                LDMX4(bh, sbh + b_off[g][0]);
                #pragma unroll
                for (int h = 0; h < 2; h++) {
                    const int nb = g * 2 + h;
                    MMA_F16(acc[0][nb], a0[0], a0[1], a0[2], a0[3], bh[2 * h], bh[2 * h + 1]);
                    MMA_F16(acc[1][nb], a1[0], a1[1], a1[2], a1[3], bh[2 * h], bh[2 * h + 1]);
                }
            }
        }

        // ---- producer work for future chunks (overlaps with ks=1 MMAs) ----
        if (kc + 1 < NUM_CHUNKS) STSA(kc + 1);   // stage (kc+1)&1 != stage kc&1
        if (kc + 2 < NUM_CHUNKS) LOADX(kc + 2);

        // ---- ks = 1 half ----
        {
            uint32_t a0[4], a1[4];
            LDMX4(a0, sa + a_off[0][1]);
            LDMX4(a1, sa + a_off[1][1]);
            #pragma unroll
            for (int g = 0; g < 4; g++) {
                uint32_t bh[4];
                LDMX4(bh, sbh + b_off[g][1]);
                #pragma unroll
                for (int h = 0; h < 2; h++) {
                    const int nb = g * 2 + h;
                    MMA_F16(acc[0][nb], a0[0], a0[1], a0[2], a0[3], bh[2 * h], bh[2 * h + 1]);
                    MMA_F16(acc[1][nb], a1[0], a1[1], a1[2], a1[3], bh[2 * h], bh[2 * h + 1]);
                }
            }
        }

        if (kc + 1 < NUM_CHUNKS) {
            if (kc + 2 < NUM_CHUNKS) CPB(kc + 2);
            CP_COMMIT();         // uniform commit keeps group arithmetic aligned
            CP_WAIT1();          // B(kc+1) (committed 2 iters ago) complete
            __syncthreads();
        }
    }

    // ---- epilogue: bias + mask-gated boundaries ----
    const float* sbias = (const float*)(smem + OFF_BIAS);
    const float* slb   = (const float*)(smem + OFF_LB);
    const float* srb   = (const float*)(smem + OFF_RB);
    const int gid = lid >> 2, tig = lid & 3;

    #pragma unroll
    for (int mb = 0; mb < 2; mb++) {
        #pragma unroll
        for (int p = 0; p < 2; p++) {
            int row = warp_m + mb * 16 + p * 8 + gid;
            int gm = blockIdx.x * M_TILE + row;
            int t = gm & (T_DIM - 1);
            int mc = mask[gm];
            int mp = (t > 0) ? mask[gm - 1] : 0;
            int mn = (t < T_DIM - 1) ? mask[gm + 1] : 0;
            float s = (mc > mp) ? 1.0f : 0.0f;
            float e = (mn > mc) ? 1.0f : 0.0f;
            float* orow = out + (size_t)gm * U_DIM;
            #pragma unroll
            for (int nb = 0; nb < 8; nb++) {
                int c = warp_n + nb * 8 + 2 * tig;
                float2 o;
                o.x = acc[mb][nb][2 * p + 0] + sbias[c + 0] + s * slb[c + 0] + e * srb[c + 0];
                o.y = acc[mb][nb][2 * p + 1] + sbias[c + 1] + s * slb[c + 1] + e * srb[c + 1];
                *reinterpret_cast<float2*>(orow + c) = o;
            }
        }
    }
}

extern "C" void kernel_launch(void* const* d_in, const int* in_sizes, int n_in,
                              void* d_out, int out_size) {
    const float* x    = (const float*)d_in[0];
    const int*   mask = (const int*)d_in[1];
    const float* kern = (const float*)d_in[2];
    const float* bias = (const float*)d_in[3];
    const float* lb   = (const float*)d_in[4];
    const float* rb   = (const float*)d_in[5];
    float* out = (float*)d_out;

    cudaFuncSetAttribute(crf_gemm_kernel,
                         cudaFuncAttributeMaxDynamicSharedMemorySize, SMEM_TOTAL);

    crf_bprep_kernel<<<(U_DIM * D_DIM) / 256, 256>>>(kern);
    crf_gemm_kernel<<<NUM_CTAS, THREADS, SMEM_TOTAL>>>(x, mask, bias, lb, rb, out);
}